// round 8
// baseline (speedup 1.0000x reference)
#include <cuda_runtime.h>
#include <cstdint>

// ---------------------------------------------------------------------------
// Problem dims
// ---------------------------------------------------------------------------
#define BATCH   4096
#define IN_DIM  1024
#define OUT_DIM 1024
#define KBIG    4096          // 4 * IN_DIM

// GEMM tiling: BM=256, BN=128, 256 threads, warp grid 4x2, warp tile 64x64.
// INT8 scheme: A,W quantized to int16 = hi8*256 + lo8 (both s8, round-nearest).
// D_int = 65536*Ahi*Whi + 256*(Ahi*Wlo + Alo*Whi)   [lo*lo dropped, ~3.5e-5]
// Mains: AhiWlo(32) + AloWhi(0..19) -> fold 256*acc to out -> AhiWhi(32).
// Helpers: AloWhi chunks [19,32) per tile -> scratch + flag.
#define BM 256
#define BN 128
#define BK 128                // int8 k-elems per chunk -> 128 B rows (SW128)
#define NCHUNK (KBIG / BK)    // 32
#define MID_MAIN 19           // AloWhi chunks done by mains
#define NTILES  128           // (4096/256) * (1024/128)
#define NHELP   24
#define NBLOCKS (NTILES + NHELP)   // 152
#define NTHREADS 256
#define TILE_A   0                        // 32 KB (256 rows x 128 B)
#define TILE_W   (BM * 128)               // 16 KB (128 rows x 128 B)
#define STAGE_BYTES  (BM * 128 + BN * 128)   // 48 KB
#define SMEM_TOTAL   (2 * STAGE_BYTES)       // 96 KB

#define QMAX 32512.0f
#define SMEM_SWIZZLE_128B(off) ((off) ^ (((off) >> 3) & 0x70))

// ---------------------------------------------------------------------------
// Device scratch (allocation-free rule: __device__ globals)
// ---------------------------------------------------------------------------
__device__ float  g_coef[BATCH * 4];
__device__ float  g_sa[BATCH];
__device__ float  g_sw[OUT_DIM];
__device__ char   g_Ahi[BATCH * KBIG];          // 16 MB
__device__ char   g_Alo[BATCH * KBIG];          // 16 MB
__device__ char   g_Whi[4 * OUT_DIM * IN_DIM];  // 4 MB
__device__ char   g_Wlo[4 * OUT_DIM * IN_DIM];  // 4 MB
__device__ float  g_scratch[BATCH * OUT_DIM];   // 16 MB helper partials
__device__ int    g_flag[NTILES];

// ---------------------------------------------------------------------------
// PTX helpers (baseline ISA only)
// ---------------------------------------------------------------------------
__device__ __forceinline__ uint32_t smem_to_u32(const void* p) {
    uint32_t a;
    asm("{ .reg .u64 t; cvta.to.shared.u64 t, %1; cvt.u32.u64 %0, t; }"
        : "=r"(a) : "l"(p));
    return a;
}

__device__ __forceinline__ void cp_async16(uint32_t saddr, const void* gaddr) {
    asm volatile("cp.async.cg.shared.global [%0], [%1], 16;"
                 :: "r"(saddr), "l"(gaddr));
}

#define CP_ASYNC_COMMIT() asm volatile("cp.async.commit_group;" ::: "memory")
#define CP_ASYNC_WAIT1()  asm volatile("cp.async.wait_group 1;" ::: "memory")
#define CP_ASYNC_WAIT0()  asm volatile("cp.async.wait_group 0;" ::: "memory")

__device__ __forceinline__ void ldsm_x4(uint32_t (&r)[4], uint32_t addr) {
    asm volatile("ldmatrix.sync.aligned.m8n8.x4.shared.b16 {%0,%1,%2,%3}, [%4];"
                 : "=r"(r[0]), "=r"(r[1]), "=r"(r[2]), "=r"(r[3]) : "r"(addr));
}

// m16n8k32 s8*s8 -> s32. Fragment thread-maps are byte-identical to the
// validated bf16 m16n8k16 ldmatrix pattern (32-byte k-step = 16 bf16).
__device__ __forceinline__ void imma_16832(int (&d)[4], const uint32_t (&a)[4],
                                           uint32_t b0, uint32_t b1) {
    asm volatile(
        "mma.sync.aligned.m16n8k32.row.col.s32.s8.s8.s32 "
        "{%0,%1,%2,%3}, {%4,%5,%6,%7}, {%8,%9}, {%0,%1,%2,%3};"
        : "+r"(d[0]), "+r"(d[1]), "+r"(d[2]), "+r"(d[3])
        : "r"(a[0]), "r"(a[1]), "r"(a[2]), "r"(a[3]), "r"(b0), "r"(b1));
}

// int16 -> (hi s8, lo s8), round-nearest hi, lo in [-128,127]
__device__ __forceinline__ void split_i16(int a16, int& hi, int& lo) {
    hi = (a16 + 128) >> 8;
    lo = a16 - (hi << 8);
}

// ---------------------------------------------------------------------------
// Kernel 1: per-row coef (CPI folded) + A quantization to int16 hi/lo planes
// ---------------------------------------------------------------------------
__global__ void __launch_bounds__(256)
quant_a_kernel(const float* __restrict__ x,
               const float* __restrict__ phase,
               const float* __restrict__ basis)
{
    __shared__ float red[256];
    const int b  = blockIdx.x;
    const int iv = threadIdx.x;

    const float HALF_PI = 1.5707963267948966f;
    float r = phase[b] / HALF_PI;
    int q = (int)floorf(r);
    q = min(max(q, 0), 3);
    float t  = r - (float)q;
    float t2 = t * t;
    float t3 = t2 * t;
    float co[4];
#pragma unroll
    for (int k = 0; k < 4; k++)
        co[k] = t3 * basis[k] + t2 * basis[4 + k] + t * basis[8 + k] + basis[12 + k];
    float cs[4];
#pragma unroll
    for (int j = 0; j < 4; j++) cs[j] = co[(j - q + 1) & 3];
    if (iv < 4) g_coef[b * 4 + iv] = cs[iv];

    float4 xv = reinterpret_cast<const float4*>(x)[b * 256 + iv];
    float mx = fmaxf(fmaxf(fabsf(xv.x), fabsf(xv.y)),
                     fmaxf(fabsf(xv.z), fabsf(xv.w)));
    red[iv] = mx;
    __syncthreads();
#pragma unroll
    for (int s = 128; s > 0; s >>= 1) {
        if (iv < s) red[iv] = fmaxf(red[iv], red[iv + s]);
        __syncthreads();
    }
    float maxx = red[0];
    float maxc = fmaxf(fmaxf(fabsf(cs[0]), fabsf(cs[1])),
                       fmaxf(fabsf(cs[2]), fabsf(cs[3])));
    float sa = fmaxf(maxx * maxc, 1e-30f) / QMAX;
    if (iv == 0) g_sa[b] = sa;
    float inv = 1.0f / sa;

    float xe[4] = {xv.x, xv.y, xv.z, xv.w};
#pragma unroll
    for (int j = 0; j < 4; j++) {
        char h[4], l[4];
#pragma unroll
        for (int e = 0; e < 4; e++) {
            int a16 = __float2int_rn(cs[j] * xe[e] * inv);
            int hi, lo;
            split_i16(a16, hi, lo);
            h[e] = (char)hi; l[e] = (char)lo;
        }
        size_t base = (size_t)b * KBIG + j * IN_DIM + iv * 4;
        *reinterpret_cast<char4*>(g_Ahi + base) = make_char4(h[0], h[1], h[2], h[3]);
        *reinterpret_cast<char4*>(g_Alo + base) = make_char4(l[0], l[1], l[2], l[3]);
    }
}

// ---------------------------------------------------------------------------
// Kernel 2: W quantization, per-output-column scale over all 4 j's
//   one block per o; also clears tile flags (block 0)
// ---------------------------------------------------------------------------
__global__ void __launch_bounds__(256)
quant_w_kernel(const float* __restrict__ w)
{
    __shared__ float red[256];
    const int o = blockIdx.x;
    const int t = threadIdx.x;

    if (o == 0 && t < NTILES) g_flag[t] = 0;

    float4 wv[4];
    float mx = 0.f;
#pragma unroll
    for (int j = 0; j < 4; j++) {
        wv[j] = *reinterpret_cast<const float4*>(
            w + ((size_t)j << 20) + (size_t)o * IN_DIM + t * 4);
        mx = fmaxf(mx, fmaxf(fmaxf(fabsf(wv[j].x), fabsf(wv[j].y)),
                             fmaxf(fabsf(wv[j].z), fabsf(wv[j].w))));
    }
    red[t] = mx;
    __syncthreads();
#pragma unroll
    for (int s = 128; s > 0; s >>= 1) {
        if (t < s) red[t] = fmaxf(red[t], red[t + s]);
        __syncthreads();
    }
    float sw = fmaxf(red[0], 1e-30f) / QMAX;
    if (t == 0) g_sw[o] = sw;
    float inv = 1.0f / sw;

#pragma unroll
    for (int j = 0; j < 4; j++) {
        float we[4] = {wv[j].x, wv[j].y, wv[j].z, wv[j].w};
        char h[4], l[4];
#pragma unroll
        for (int e = 0; e < 4; e++) {
            int w16 = __float2int_rn(we[e] * inv);
            int hi, lo;
            split_i16(w16, hi, lo);
            h[e] = (char)hi; l[e] = (char)lo;
        }
        size_t base = ((size_t)j << 20) + (size_t)o * IN_DIM + t * 4;
        *reinterpret_cast<char4*>(g_Whi + base) = make_char4(h[0], h[1], h[2], h[3]);
        *reinterpret_cast<char4*>(g_Wlo + base) = make_char4(l[0], l[1], l[2], l[3]);
    }
}

// ---------------------------------------------------------------------------
// Kernel 3: IMMA s8 GEMM
// ---------------------------------------------------------------------------
__device__ __forceinline__ void issue_tile_load(
    uint32_t smem_base, int stage, const char* __restrict__ Ap,
    const char* __restrict__ Wp, int ck, int tid, int mBase, int nBase)
{
    const int kA = ck * BK;               // element == byte offset within row
    const int j  = kA >> 10;
    const int i0 = kA & (IN_DIM - 1);
    const char* __restrict__ Wb = Wp + ((size_t)j << 20) + i0;

    const uint32_t st = smem_base + stage * STAGE_BYTES;

    // A: 256 rows x 8 vec16 = 2048 -> 8 per thread
#pragma unroll
    for (int it = 0; it < 8; it++) {
        int idx = tid + it * NTHREADS;
        int row = idx >> 3;
        int cv  = idx & 7;
        const void* g = Ap + (size_t)(mBase + row) * KBIG + kA + cv * 16;
        cp_async16(st + TILE_A + SMEM_SWIZZLE_128B(row * 128 + cv * 16), g);
    }
    // W: 128 rows x 8 vec16 = 1024 -> 4 per thread
#pragma unroll
    for (int it = 0; it < 4; it++) {
        int idx = tid + it * NTHREADS;
        int row = idx >> 3;
        int cv  = idx & 7;
        const void* g = Wb + (size_t)(nBase + row) * IN_DIM + cv * 16;
        cp_async16(st + TILE_W + SMEM_SWIZZLE_128B(row * 128 + cv * 16), g);
    }
}

__device__ __forceinline__ void run_chunks(
    uint32_t smem_base, int tid, int lane, int wm, int wn,
    int mBase, int nBase, const char* __restrict__ Ap,
    const char* __restrict__ Wp, int ck0, int nck, int (&acc)[4][8][4])
{
    const int a_row  = lane & 15;
    const int a_colh = (lane >> 4) * 16;
    const int b_row  = (lane & 7) + ((lane >> 4) << 3);
    const int b_colh = ((lane >> 3) & 1) * 16;

    issue_tile_load(smem_base, 0, Ap, Wp, ck0, tid, mBase, nBase);
    CP_ASYNC_COMMIT();
    issue_tile_load(smem_base, 1, Ap, Wp, ck0 + 1, tid, mBase, nBase);
    CP_ASYNC_COMMIT();

#pragma unroll 1
    for (int i = 0; i < nck; i++) {
        CP_ASYNC_WAIT1();
        __syncthreads();

        const uint32_t st = smem_base + (i & 1) * STAGE_BYTES;
        const uint32_t sa = st + TILE_A;
        const uint32_t sw = st + TILE_W;

#pragma unroll
        for (int ks = 0; ks < 4; ks++) {     // 4 x k32 within BK=128
            const int kc = ks * 32;
            uint32_t aF[4][4];
#pragma unroll
            for (int mt = 0; mt < 4; mt++) {
                uint32_t off = SMEM_SWIZZLE_128B(
                    (wm * 64 + mt * 16 + a_row) * 128 + kc + a_colh);
                ldsm_x4(aF[mt], sa + off);
            }
            uint32_t bF[8][2];
#pragma unroll
            for (int nt2 = 0; nt2 < 4; nt2++) {
                uint32_t b4[4];
                uint32_t off = SMEM_SWIZZLE_128B(
                    (wn * 64 + nt2 * 16 + b_row) * 128 + kc + b_colh);
                ldsm_x4(b4, sw + off);
                bF[nt2 * 2 + 0][0] = b4[0]; bF[nt2 * 2 + 0][1] = b4[1];
                bF[nt2 * 2 + 1][0] = b4[2]; bF[nt2 * 2 + 1][1] = b4[3];
            }
#pragma unroll
            for (int mt = 0; mt < 4; mt++)
#pragma unroll
                for (int nt = 0; nt < 8; nt++)
                    imma_16832(acc[mt][nt], aF[mt], bF[nt][0], bF[nt][1]);
        }

        __syncthreads();
        {
            int lck = i + 2;
            if (lck < nck)
                issue_tile_load(smem_base, i & 1, Ap, Wp, ck0 + lck,
                                tid, mBase, nBase);
            CP_ASYNC_COMMIT();
        }
    }
    CP_ASYNC_WAIT0();
}

__device__ __forceinline__ void zero_acc(int (&acc)[4][8][4])
{
#pragma unroll
    for (int i = 0; i < 4; i++)
#pragma unroll
        for (int j = 0; j < 8; j++)
#pragma unroll
            for (int k = 0; k < 4; k++) acc[i][j][k] = 0;
}

__global__ void __launch_bounds__(NTHREADS, 1)
gemm_kernel(const float* __restrict__ biases, float* __restrict__ out)
{
    extern __shared__ char smem[];
    const uint32_t smem_base = smem_to_u32(smem);
    const int tid  = threadIdx.x;
    const int wid  = tid >> 5;
    const int lane = tid & 31;
    const int wm   = wid & 3;    // 4 warp rows (64 rows each)
    const int wn   = wid >> 2;   // 2 warp cols (64 cols each)
    const int tg   = lane >> 2;
    const int tc   = (lane & 3) * 2;

    int acc[4][8][4];

    if (blockIdx.x < NHELP) {
        // ---------- HELPER: AloWhi chunks [MID_MAIN, 32) per assigned tile ----
        const int h = blockIdx.x;
#pragma unroll 1
        for (int t = h; t < NTILES; t += NHELP) {
            const int mBase = (t & 15) * BM;
            const int nBase = (t >> 4) * BN;
            zero_acc(acc);
            run_chunks(smem_base, tid, lane, wm, wn, mBase, nBase,
                       g_Alo, g_Whi, MID_MAIN, NCHUNK - MID_MAIN, acc);
#pragma unroll
            for (int nt = 0; nt < 8; nt++) {
                int col = nBase + wn * 64 + nt * 8 + tc;
#pragma unroll
                for (int mt = 0; mt < 4; mt++) {
                    int r0 = mBase + wm * 64 + mt * 16 + tg;
                    float2 r01 = make_float2(256.f * (float)acc[mt][nt][0],
                                             256.f * (float)acc[mt][nt][1]);
                    float2 r23 = make_float2(256.f * (float)acc[mt][nt][2],
                                             256.f * (float)acc[mt][nt][3]);
                    *reinterpret_cast<float2*>(g_scratch + (size_t)r0 * OUT_DIM + col) = r01;
                    *reinterpret_cast<float2*>(g_scratch + (size_t)(r0 + 8) * OUT_DIM + col) = r23;
                }
            }
            __threadfence();
            __syncthreads();
            if (tid == 0)
                asm volatile("st.release.gpu.global.b32 [%0], %1;"
                             :: "l"(&g_flag[t]), "r"(1) : "memory");
            __syncthreads();
        }
        return;
    }

    // ---------------- MAIN CTA ----------------
    const int t = blockIdx.x - NHELP;
    const int mBase = (t & 15) * BM;
    const int nBase = (t >> 4) * BN;

    // Phase 1: mid products (weight 256): Ahi*Wlo full + Alo*Whi [0, MID_MAIN)
    zero_acc(acc);
    run_chunks(smem_base, tid, lane, wm, wn, mBase, nBase,
               g_Ahi, g_Wlo, 0, NCHUNK, acc);
    run_chunks(smem_base, tid, lane, wm, wn, mBase, nBase,
               g_Alo, g_Whi, 0, MID_MAIN, acc);

    // Fold: out <- 256 * acc   (same-thread readback later)
#pragma unroll
    for (int nt = 0; nt < 8; nt++) {
        int col = nBase + wn * 64 + nt * 8 + tc;
#pragma unroll
        for (int mt = 0; mt < 4; mt++) {
            int r0 = mBase + wm * 64 + mt * 16 + tg;
            float2 r01 = make_float2(256.f * (float)acc[mt][nt][0],
                                     256.f * (float)acc[mt][nt][1]);
            float2 r23 = make_float2(256.f * (float)acc[mt][nt][2],
                                     256.f * (float)acc[mt][nt][3]);
            *reinterpret_cast<float2*>(out + (size_t)r0 * OUT_DIM + col) = r01;
            *reinterpret_cast<float2*>(out + (size_t)(r0 + 8) * OUT_DIM + col) = r23;
        }
    }

    // Phase 2: hi*hi (weight 65536)
    zero_acc(acc);
    run_chunks(smem_base, tid, lane, wm, wn, mBase, nBase,
               g_Ahi, g_Whi, 0, NCHUNK, acc);

    // Wait for helper partial
    if (tid == 0) {
        int f;
        do {
            asm volatile("ld.acquire.gpu.global.b32 %0, [%1];"
                         : "=r"(f) : "l"(&g_flag[t]) : "memory");
            if (!f) __nanosleep(128);
        } while (!f);
    }
    __syncthreads();

    // Epilogue: out = sa[b]*sw[o]*(65536*acc + out_mid + scratch) + sum_j c_j b_j
    float cA[4][4], cB[4][4], sa0[4], sa1[4];
#pragma unroll
    for (int mt = 0; mt < 4; mt++) {
        int r0 = mBase + wm * 64 + mt * 16 + tg;
        sa0[mt] = g_sa[r0];
        sa1[mt] = g_sa[r0 + 8];
#pragma unroll
        for (int j = 0; j < 4; j++) {
            cA[mt][j] = g_coef[r0 * 4 + j];
            cB[mt][j] = g_coef[(r0 + 8) * 4 + j];
        }
    }

#pragma unroll
    for (int nt = 0; nt < 8; nt++) {
        int col = nBase + wn * 64 + nt * 8 + tc;
        float2 swv = *reinterpret_cast<const float2*>(g_sw + col);
        float2 bj[4];
#pragma unroll
        for (int j = 0; j < 4; j++)
            bj[j] = *reinterpret_cast<const float2*>(biases + j * OUT_DIM + col);
#pragma unroll
        for (int mt = 0; mt < 4; mt++) {
            int r0 = mBase + wm * 64 + mt * 16 + tg;
            float2 m01 = *reinterpret_cast<const float2*>(out + (size_t)r0 * OUT_DIM + col);
            float2 m23 = *reinterpret_cast<const float2*>(out + (size_t)(r0 + 8) * OUT_DIM + col);
            float2 s01 = *reinterpret_cast<const float2*>(g_scratch + (size_t)r0 * OUT_DIM + col);
            float2 s23 = *reinterpret_cast<const float2*>(g_scratch + (size_t)(r0 + 8) * OUT_DIM + col);
            float be0 = 0.f, be1 = 0.f, be2 = 0.f, be3 = 0.f;
#pragma unroll
            for (int j = 0; j < 4; j++) {
                be0 += cA[mt][j] * bj[j].x;
                be1 += cA[mt][j] * bj[j].y;
                be2 += cB[mt][j] * bj[j].x;
                be3 += cB[mt][j] * bj[j].y;
            }
            float2 r01, r23;
            r01.x = sa0[mt] * swv.x * (65536.f * (float)acc[mt][nt][0] + m01.x + s01.x) + be0;
            r01.y = sa0[mt] * swv.y * (65536.f * (float)acc[mt][nt][1] + m01.y + s01.y) + be1;
            r23.x = sa1[mt] * swv.x * (65536.f * (float)acc[mt][nt][2] + m23.x + s23.x) + be2;
            r23.y = sa1[mt] * swv.y * (65536.f * (float)acc[mt][nt][3] + m23.y + s23.y) + be3;
            *reinterpret_cast<float2*>(out + (size_t)r0 * OUT_DIM + col) = r01;
            *reinterpret_cast<float2*>(out + (size_t)(r0 + 8) * OUT_DIM + col) = r23;
        }
    }
}

// ---------------------------------------------------------------------------
// kernel_launch
// ---------------------------------------------------------------------------
extern "C" void kernel_launch(void* const* d_in, const int* in_sizes, int n_in,
                              void* d_out, int out_size)
{
    const float* x      = (const float*)d_in[0];
    const float* phase  = (const float*)d_in[1];
    const float* w      = (const float*)d_in[2];
    const float* biases = (const float*)d_in[3];
    const float* basis  = (const float*)d_in[4];
    float* out = (float*)d_out;

    static bool attr_set = false;
    if (!attr_set) {
        cudaFuncSetAttribute(gemm_kernel,
                             cudaFuncAttributeMaxDynamicSharedMemorySize,
                             SMEM_TOTAL);
        attr_set = true;
    }

    quant_a_kernel<<<BATCH, 256>>>(x, phase, basis);
    quant_w_kernel<<<OUT_DIM, 256>>>(w);

    gemm_kernel<<<NBLOCKS, NTHREADS, SMEM_TOTAL>>>(biases, out);
}

// round 10
// speedup vs baseline: 2.9382x; 2.9382x over previous
#include <cuda_runtime.h>
#include <cuda_bf16.h>
#include <cstdint>

// ---------------------------------------------------------------------------
// Problem dims
// ---------------------------------------------------------------------------
#define BATCH   4096
#define IN_DIM  1024
#define OUT_DIM 1024
#define KBIG    4096          // 4 * IN_DIM

// GEMM tiling: BM=256, BN=128, 256 threads, warp grid 4x2, warp tile 64x64.
// Fused-3-segment iteration (Ah*Wh + Al*Wh + Ah*Wl into one accumulator).
// K-split: mains do chunks [0,57), 24 helpers do [57,64) x 5-6 tiles each.
#define BM 256
#define BN 128
#define BK 64                 // bf16 -> 128 bytes per row
#define NCHUNK (KBIG / BK)    // 64
#define CK_MAIN 57            // chunks done by main CTAs (balanced vs helpers)
#define NTILES  128           // (4096/256) * (1024/128)
#define NHELP   24
#define NBLOCKS (NTILES + NHELP)   // 152
#define STAGES 2
#define NTHREADS 256
#define TILE_AH  0                         // 32 KB
#define TILE_AL  (BM * 128)                // 32 KB
#define TILE_WH  (2 * BM * 128)            // 16 KB
#define TILE_WL  (2 * BM * 128 + BN * 128) // 16 KB
#define STAGE_BYTES  (2 * BM * 128 + 2 * BN * 128)   // 96 KB
#define SMEM_TOTAL   (STAGES * STAGE_BYTES)          // 192 KB

#define SMEM_SWIZZLE_128B(off) ((off) ^ (((off) >> 3) & 0x70))

// ---------------------------------------------------------------------------
// Device scratch (allocation-free rule: __device__ globals)
// ---------------------------------------------------------------------------
__device__ float          g_coef[BATCH * 4];
__device__ __nv_bfloat16  g_Ah[BATCH * KBIG];         // 32 MB
__device__ __nv_bfloat16  g_Al[BATCH * KBIG];         // 32 MB
__device__ __nv_bfloat16  g_Wh[4 * OUT_DIM * IN_DIM]; // 8 MB
__device__ __nv_bfloat16  g_Wl[4 * OUT_DIM * IN_DIM]; // 8 MB
__device__ float          g_scratch[BATCH * OUT_DIM]; // 16 MB helper partials
__device__ int            g_flag[NTILES];

// ---------------------------------------------------------------------------
// PTX helpers (baseline ISA only)
// ---------------------------------------------------------------------------
__device__ __forceinline__ uint32_t smem_to_u32(const void* p) {
    uint32_t a;
    asm("{ .reg .u64 t; cvta.to.shared.u64 t, %1; cvt.u32.u64 %0, t; }"
        : "=r"(a) : "l"(p));
    return a;
}

__device__ __forceinline__ void cp_async16(uint32_t saddr, const void* gaddr) {
    asm volatile("cp.async.cg.shared.global [%0], [%1], 16;"
                 :: "r"(saddr), "l"(gaddr));
}

#define CP_ASYNC_COMMIT() asm volatile("cp.async.commit_group;" ::: "memory")
#define CP_ASYNC_WAIT1()  asm volatile("cp.async.wait_group 1;" ::: "memory")
#define CP_ASYNC_WAIT0()  asm volatile("cp.async.wait_group 0;" ::: "memory")

__device__ __forceinline__ void ldsm_x4(uint32_t (&r)[4], uint32_t addr) {
    asm volatile("ldmatrix.sync.aligned.m8n8.x4.shared.b16 {%0,%1,%2,%3}, [%4];"
                 : "=r"(r[0]), "=r"(r[1]), "=r"(r[2]), "=r"(r[3]) : "r"(addr));
}

__device__ __forceinline__ void mma_16816(float (&d)[4], const uint32_t (&a)[4],
                                          uint32_t b0, uint32_t b1) {
    asm volatile(
        "mma.sync.aligned.m16n8k16.row.col.f32.bf16.bf16.f32 "
        "{%0,%1,%2,%3}, {%4,%5,%6,%7}, {%8,%9}, {%0,%1,%2,%3};"
        : "+f"(d[0]), "+f"(d[1]), "+f"(d[2]), "+f"(d[3])
        : "r"(a[0]), "r"(a[1]), "r"(a[2]), "r"(a[3]), "r"(b0), "r"(b1));
}

// ---------------------------------------------------------------------------
// Split helpers
// ---------------------------------------------------------------------------
__device__ __forceinline__ uint32_t pack2bf16(__nv_bfloat16 lo, __nv_bfloat16 hi)
{
    return ((uint32_t)__bfloat16_as_ushort(hi) << 16) |
           (uint32_t)__bfloat16_as_ushort(lo);
}

__device__ __forceinline__ void split1(float a, __nv_bfloat16& h, __nv_bfloat16& l)
{
    h = __float2bfloat16(a);
    l = __float2bfloat16(a - __bfloat162float(h));
}

// ---------------------------------------------------------------------------
// Kernel 1 (merged preprocessing):
//   blocks [0, BATCH):             coef + A = c*x split into bf16 hi/lo
//   blocks [BATCH, BATCH+1024):    weights -> bf16 hi/lo
//     W total = 4*1024*1024 floats = 1,048,576 float4
//     1024 blocks x 256 threads x 4 iters = 1,048,576  (exact)
// ---------------------------------------------------------------------------
__global__ void __launch_bounds__(256)
prep_kernel(const float* __restrict__ x,
            const float* __restrict__ phase,
            const float* __restrict__ basis,
            const float* __restrict__ w)
{
    const int iv = threadIdx.x;

    if (blockIdx.x >= BATCH) {
        const int blk = blockIdx.x - BATCH;          // 0..1023
        if (blk == 0 && iv < NTILES) g_flag[iv] = 0; // per-launch flag clear
        size_t t0 = (size_t)blk * 1024 + iv;         // float4 index
#pragma unroll
        for (int r = 0; r < 4; r++) {
            size_t t = t0 + (size_t)r * 256;
            float4 wv = reinterpret_cast<const float4*>(w)[t];
            __nv_bfloat16 h0, h1, h2, h3, l0, l1, l2, l3;
            split1(wv.x, h0, l0); split1(wv.y, h1, l1);
            split1(wv.z, h2, l2); split1(wv.w, h3, l3);
            size_t base = t * 4;
            uint2 vh = make_uint2(pack2bf16(h0, h1), pack2bf16(h2, h3));
            uint2 vl = make_uint2(pack2bf16(l0, l1), pack2bf16(l2, l3));
            *reinterpret_cast<uint2*>(g_Wh + base) = vh;
            *reinterpret_cast<uint2*>(g_Wl + base) = vl;
        }
        return;
    }

    // ---- A split: one block per batch row ----
    const int b = blockIdx.x;
    const float HALF_PI = 1.5707963267948966f;
    float r = phase[b] / HALF_PI;
    int q = (int)floorf(r);
    q = min(max(q, 0), 3);
    float t  = r - (float)q;
    float t2 = t * t;
    float t3 = t2 * t;
    float co[4];
#pragma unroll
    for (int k = 0; k < 4; k++)
        co[k] = t3 * basis[k] + t2 * basis[4 + k] + t * basis[8 + k] + basis[12 + k];
    float cs[4];
#pragma unroll
    for (int j = 0; j < 4; j++) cs[j] = co[(j - q + 1) & 3];
    if (iv < 4) g_coef[b * 4 + iv] = cs[iv];

    float4 xv = reinterpret_cast<const float4*>(x)[b * 256 + iv];
#pragma unroll
    for (int j = 0; j < 4; j++) {
        float a0 = cs[j] * xv.x, a1 = cs[j] * xv.y;
        float a2 = cs[j] * xv.z, a3 = cs[j] * xv.w;
        __nv_bfloat16 h0, h1, h2, h3, l0, l1, l2, l3;
        split1(a0, h0, l0); split1(a1, h1, l1);
        split1(a2, h2, l2); split1(a3, h3, l3);
        size_t base = (size_t)b * KBIG + j * IN_DIM + iv * 4;
        uint2 vh = make_uint2(pack2bf16(h0, h1), pack2bf16(h2, h3));
        uint2 vl = make_uint2(pack2bf16(l0, l1), pack2bf16(l2, l3));
        *reinterpret_cast<uint2*>(g_Ah + base) = vh;
        *reinterpret_cast<uint2*>(g_Al + base) = vl;
    }
}

// ---------------------------------------------------------------------------
// Kernel 2: fused-3-segment mma.sync bf16 GEMM with K-split helpers
// ---------------------------------------------------------------------------
__device__ __forceinline__ void issue_tile_load(
    uint32_t smem_base, int stage, int ck, int tid, int mBase, int nBase)
{
    const int kA = ck * BK;
    const int j  = kA >> 10;
    const int i0 = kA & (IN_DIM - 1);
    const size_t wOff = (size_t)j * (OUT_DIM * IN_DIM) + i0;

    const uint32_t st = smem_base + stage * STAGE_BYTES;

#pragma unroll
    for (int it = 0; it < 8; it++) {
        int idx = tid + it * NTHREADS;
        int row = idx >> 3;
        int cv  = idx & 7;
        size_t goff = (size_t)(mBase + row) * KBIG + kA + cv * 8;
        uint32_t soff = SMEM_SWIZZLE_128B(row * 128 + cv * 16);
        cp_async16(st + TILE_AH + soff, g_Ah + goff);
        cp_async16(st + TILE_AL + soff, g_Al + goff);
    }
#pragma unroll
    for (int it = 0; it < 4; it++) {
        int idx = tid + it * NTHREADS;
        int row = idx >> 3;
        int cv  = idx & 7;
        size_t goff = wOff + (size_t)(nBase + row) * IN_DIM + cv * 8;
        uint32_t soff = SMEM_SWIZZLE_128B(row * 128 + cv * 16);
        cp_async16(st + TILE_WH + soff, g_Wh + goff);
        cp_async16(st + TILE_WL + soff, g_Wl + goff);
    }
}

// Run nck chunks [ck0, ck0+nck) of the fused K loop, accumulating into acc.
__device__ __forceinline__ void run_chunks(
    uint32_t smem_base, int tid, int lane, int wm, int wn,
    int mBase, int nBase, int ck0, int nck, float (&acc)[4][8][4])
{
    const int a_row  = lane & 15;
    const int a_colh = (lane >> 4) * 16;
    const int b_row  = (lane & 7) + ((lane >> 4) << 3);
    const int b_colh = ((lane >> 3) & 1) * 16;

    issue_tile_load(smem_base, 0, ck0, tid, mBase, nBase);
    CP_ASYNC_COMMIT();
    issue_tile_load(smem_base, 1, ck0 + 1, tid, mBase, nBase);
    CP_ASYNC_COMMIT();

#pragma unroll 1
    for (int i = 0; i < nck; i++) {
        CP_ASYNC_WAIT1();
        __syncthreads();

        const uint32_t st = smem_base + (i & 1) * STAGE_BYTES;
        const uint32_t sah = st + TILE_AH;
        const uint32_t sal = st + TILE_AL;
        const uint32_t swh = st + TILE_WH;
        const uint32_t swl = st + TILE_WL;

#pragma unroll
        for (int ks = 0; ks < 4; ks++) {
            const int kc = ks * 32;
            uint32_t aH[4][4], aL[4][4];
#pragma unroll
            for (int mt = 0; mt < 4; mt++) {
                uint32_t off = SMEM_SWIZZLE_128B(
                    (wm * 64 + mt * 16 + a_row) * 128 + kc + a_colh);
                ldsm_x4(aH[mt], sah + off);
                ldsm_x4(aL[mt], sal + off);
            }
            {
                uint32_t bH[8][2];
#pragma unroll
                for (int nt2 = 0; nt2 < 4; nt2++) {
                    uint32_t b4[4];
                    uint32_t off = SMEM_SWIZZLE_128B(
                        (wn * 64 + nt2 * 16 + b_row) * 128 + kc + b_colh);
                    ldsm_x4(b4, swh + off);
                    bH[nt2 * 2 + 0][0] = b4[0]; bH[nt2 * 2 + 0][1] = b4[1];
                    bH[nt2 * 2 + 1][0] = b4[2]; bH[nt2 * 2 + 1][1] = b4[3];
                }
#pragma unroll
                for (int mt = 0; mt < 4; mt++)
#pragma unroll
                    for (int nt = 0; nt < 8; nt++)
                        mma_16816(acc[mt][nt], aH[mt], bH[nt][0], bH[nt][1]);
#pragma unroll
                for (int mt = 0; mt < 4; mt++)
#pragma unroll
                    for (int nt = 0; nt < 8; nt++)
                        mma_16816(acc[mt][nt], aL[mt], bH[nt][0], bH[nt][1]);
            }
            {
                uint32_t bL[8][2];
#pragma unroll
                for (int nt2 = 0; nt2 < 4; nt2++) {
                    uint32_t b4[4];
                    uint32_t off = SMEM_SWIZZLE_128B(
                        (wn * 64 + nt2 * 16 + b_row) * 128 + kc + b_colh);
                    ldsm_x4(b4, swl + off);
                    bL[nt2 * 2 + 0][0] = b4[0]; bL[nt2 * 2 + 0][1] = b4[1];
                    bL[nt2 * 2 + 1][0] = b4[2]; bL[nt2 * 2 + 1][1] = b4[3];
                }
#pragma unroll
                for (int mt = 0; mt < 4; mt++)
#pragma unroll
                    for (int nt = 0; nt < 8; nt++)
                        mma_16816(acc[mt][nt], aH[mt], bL[nt][0], bL[nt][1]);
            }
        }

        __syncthreads();
        {
            int lck = i + STAGES;
            if (lck < nck)
                issue_tile_load(smem_base, i & 1, ck0 + lck, tid, mBase, nBase);
            CP_ASYNC_COMMIT();
        }
    }
    CP_ASYNC_WAIT0();
}

__global__ void __launch_bounds__(NTHREADS, 1)
gemm_kernel(const float* __restrict__ biases, float* __restrict__ out)
{
    extern __shared__ char smem[];
    const uint32_t smem_base = smem_to_u32(smem);
    const int tid  = threadIdx.x;
    const int wid  = tid >> 5;
    const int lane = tid & 31;
    const int wm   = wid & 3;    // 4 warp rows (64 rows each)
    const int wn   = wid >> 2;   // 2 warp cols (64 cols each)
    const int tg   = lane >> 2;
    const int tc   = (lane & 3) * 2;

    if (blockIdx.x < NHELP) {
        // ------------------- HELPER CTA: chunks [CK_MAIN, 64) -------------------
        const int h = blockIdx.x;
#pragma unroll 1
        for (int t = h; t < NTILES; t += NHELP) {
            const int mBase = (t & 15) * BM;
            const int nBase = (t >> 4) * BN;

            float acc[4][8][4];
#pragma unroll
            for (int i = 0; i < 4; i++)
#pragma unroll
                for (int j = 0; j < 8; j++)
#pragma unroll
                    for (int k = 0; k < 4; k++) acc[i][j][k] = 0.f;

            run_chunks(smem_base, tid, lane, wm, wn, mBase, nBase,
                       CK_MAIN, NCHUNK - CK_MAIN, acc);

#pragma unroll
            for (int nt = 0; nt < 8; nt++) {
                int col = nBase + wn * 64 + nt * 8 + tc;
#pragma unroll
                for (int mt = 0; mt < 4; mt++) {
                    int r0 = mBase + wm * 64 + mt * 16 + tg;
                    float2 r01 = make_float2(acc[mt][nt][0], acc[mt][nt][1]);
                    float2 r23 = make_float2(acc[mt][nt][2], acc[mt][nt][3]);
                    *reinterpret_cast<float2*>(g_scratch + (size_t)r0 * OUT_DIM + col) = r01;
                    *reinterpret_cast<float2*>(g_scratch + (size_t)(r0 + 8) * OUT_DIM + col) = r23;
                }
            }
            __threadfence();
            __syncthreads();
            if (tid == 0) {
                asm volatile("st.release.gpu.global.b32 [%0], %1;"
                             :: "l"(&g_flag[t]), "r"(1) : "memory");
            }
            __syncthreads();
        }
        return;
    }

    // --------------------- MAIN CTA: chunks [0, CK_MAIN) ---------------------
    const int t = blockIdx.x - NHELP;
    const int mBase = (t & 15) * BM;
    const int nBase = (t >> 4) * BN;

    float acc[4][8][4];
#pragma unroll
    for (int i = 0; i < 4; i++)
#pragma unroll
        for (int j = 0; j < 8; j++)
#pragma unroll
            for (int k = 0; k < 4; k++) acc[i][j][k] = 0.f;

    run_chunks(smem_base, tid, lane, wm, wn, mBase, nBase, 0, CK_MAIN, acc);

    // Wait for helper partial (helpers finish earlier by construction)
    if (tid == 0) {
        int f;
        do {
            asm volatile("ld.acquire.gpu.global.b32 %0, [%1];"
                         : "=r"(f) : "l"(&g_flag[t]) : "memory");
            if (!f) __nanosleep(64);
        } while (!f);
    }
    __syncthreads();

    // ---- Epilogue: D += scratch + sum_j c_j[b] * bias_j[o] ----
    float cA[4][4], cB[4][4];
#pragma unroll
    for (int mt = 0; mt < 4; mt++) {
        int r0 = mBase + wm * 64 + mt * 16 + tg;
#pragma unroll
        for (int j = 0; j < 4; j++) {
            cA[mt][j] = g_coef[r0 * 4 + j];
            cB[mt][j] = g_coef[(r0 + 8) * 4 + j];
        }
    }

#pragma unroll
    for (int nt = 0; nt < 8; nt++) {
        int col = nBase + wn * 64 + nt * 8 + tc;
        float2 bj[4];
#pragma unroll
        for (int j = 0; j < 4; j++)
            bj[j] = *reinterpret_cast<const float2*>(biases + j * OUT_DIM + col);
#pragma unroll
        for (int mt = 0; mt < 4; mt++) {
            int r0 = mBase + wm * 64 + mt * 16 + tg;
            float2 s01 = *reinterpret_cast<const float2*>(g_scratch + (size_t)r0 * OUT_DIM + col);
            float2 s23 = *reinterpret_cast<const float2*>(g_scratch + (size_t)(r0 + 8) * OUT_DIM + col);
            float be0 = 0.f, be1 = 0.f, be2 = 0.f, be3 = 0.f;
#pragma unroll
            for (int j = 0; j < 4; j++) {
                be0 += cA[mt][j] * bj[j].x;
                be1 += cA[mt][j] * bj[j].y;
                be2 += cB[mt][j] * bj[j].x;
                be3 += cB[mt][j] * bj[j].y;
            }
            float2 r01 = make_float2(acc[mt][nt][0] + be0 + s01.x,
                                     acc[mt][nt][1] + be1 + s01.y);
            float2 r23 = make_float2(acc[mt][nt][2] + be2 + s23.x,
                                     acc[mt][nt][3] + be3 + s23.y);
            *reinterpret_cast<float2*>(out + (size_t)r0 * OUT_DIM + col) = r01;
            *reinterpret_cast<float2*>(out + (size_t)(r0 + 8) * OUT_DIM + col) = r23;
        }
    }
}

// ---------------------------------------------------------------------------
// kernel_launch
// ---------------------------------------------------------------------------
extern "C" void kernel_launch(void* const* d_in, const int* in_sizes, int n_in,
                              void* d_out, int out_size)
{
    const float* x      = (const float*)d_in[0];
    const float* phase  = (const float*)d_in[1];
    const float* w      = (const float*)d_in[2];
    const float* biases = (const float*)d_in[3];
    const float* basis  = (const float*)d_in[4];
    float* out = (float*)d_out;

    static bool attr_set = false;
    if (!attr_set) {
        cudaFuncSetAttribute(gemm_kernel,
                             cudaFuncAttributeMaxDynamicSharedMemorySize,
                             SMEM_TOTAL);
        attr_set = true;
    }

    prep_kernel<<<BATCH + 1024, 256>>>(x, phase, basis, w);
    gemm_kernel<<<NBLOCKS, NTHREADS, SMEM_TOTAL>>>(biases, out);
}